// round 6
// baseline (speedup 1.0000x reference)
#include <cuda_runtime.h>
#include <cstdint>

// Problem constants: N=100000, E=1000000, H=8, C=10, HC=80
#define NN   100000
#define EE   1000000
#define HC   80
#define H    8
#define C    10

typedef unsigned long long u64;

// ---------------- packed f32x2 helpers (Blackwell FFMA2) ---------------------
__device__ __forceinline__ u64 fma2(u64 a, u64 b, u64 c) {
    u64 d;
    asm("fma.rn.f32x2 %0, %1, %2, %3;" : "=l"(d) : "l"(a), "l"(b), "l"(c));
    return d;
}
__device__ __forceinline__ float2 unpack2(u64 v) {
    float lo, hi;
    asm("mov.b64 {%0, %1}, %2;" : "=f"(lo), "=f"(hi) : "l"(v));
    return make_float2(lo, hi);
}

// ---------------- scratch (device globals) -----------------------------------
__device__ float g_xl[(size_t)NN * HC];   // Wl x  (source transform)
__device__ float g_xr[(size_t)NN * HC];   // Wr x  (target transform)
__device__ float g_h[(size_t)NN * HC];    // layer activations (next input)
__device__ int   g_deg[NN];
__device__ int   g_rowptr[NN + 1];
__device__ int   g_cursor[NN];
__device__ int   g_csr[EE];               // src indices grouped by dst
__device__ int   g_bh[64];                // degree-bucket histogram
__device__ int   g_bhoff[64];
__device__ int   g_bcur[64];
__device__ int   g_perm[NN];              // nodes sorted by degree

// ---------------- fused GEMM: Yl = X@Wl, Yr = X@Wr  (f32x2, dup-W) -----------
// 256 threads, 128 rows/block. Thread: 8 rows x (5 Wl + 5 Wr) cols, cols
// tx+16j. W staged pre-duplicated as (w,w) pairs -> inner loop has no packs.
template <int DIN, int KC>
__global__ __launch_bounds__(256, 2) void gemm2(
    const float* __restrict__ X, const float* __restrict__ Wl,
    const float* __restrict__ Wr, float* __restrict__ Yl,
    float* __restrict__ Yr, int N) {
    extern __shared__ float sm[];
    float* xs = sm;                          // [KC][132] k-major, padded
    u64*   wb = (u64*)(sm + KC * 132);       // [KC][160] dup pairs (Wl|Wr)

    const int tid = threadIdx.x;
    const int row0 = blockIdx.x * 128;
    const int tx = tid & 15, ty = tid >> 4;
    const int r0 = ty * 8;

    u64 acc[10][4];
#pragma unroll
    for (int j = 0; j < 10; j++)
#pragma unroll
        for (int i = 0; i < 4; i++) acc[j][i] = 0ull;

    for (int k0 = 0; k0 < DIN; k0 += KC) {
        __syncthreads();
        // X chunk: i = kq*128 + r -> conflict-free smem stores
        for (int i = tid; i < 128 * (KC / 4); i += 256) {
            int kq = i >> 7, r = i & 127;
            int gr = row0 + r;
            float4 v = make_float4(0.f, 0.f, 0.f, 0.f);
            if (gr < N) v = *(const float4*)(X + (size_t)gr * DIN + k0 + kq * 4);
            xs[(kq * 4 + 0) * 132 + r] = v.x;
            xs[(kq * 4 + 1) * 132 + r] = v.y;
            xs[(kq * 4 + 2) * 132 + r] = v.z;
            xs[(kq * 4 + 3) * 132 + r] = v.w;
        }
        // W chunks: store duplicated pairs
        for (int i = tid; i < KC * 80; i += 256) {
            int k = i / 80, c = i - k * 80;
            float vl = Wl[(size_t)(k0 + k) * 80 + c];
            float vr = Wr[(size_t)(k0 + k) * 80 + c];
            ((float2*)wb)[k * 160 + c] = make_float2(vl, vl);
            ((float2*)wb)[k * 160 + 80 + c] = make_float2(vr, vr);
        }
        __syncthreads();

#pragma unroll 4
        for (int k = 0; k < KC; k++) {
            ulonglong2 xa = *(const ulonglong2*)&xs[k * 132 + r0];
            ulonglong2 xb = *(const ulonglong2*)&xs[k * 132 + r0 + 4];
            u64 xf[4] = {xa.x, xa.y, xb.x, xb.y};
            u64 wp[10];
#pragma unroll
            for (int j = 0; j < 5; j++) {
                wp[j] = wb[k * 160 + tx + 16 * j];
                wp[5 + j] = wb[k * 160 + 80 + tx + 16 * j];
            }
#pragma unroll
            for (int j = 0; j < 10; j++)
#pragma unroll
                for (int i = 0; i < 4; i++)
                    acc[j][i] = fma2(wp[j], xf[i], acc[j][i]);
        }
    }

#pragma unroll
    for (int i = 0; i < 4; i++) {
        int ga = row0 + r0 + 2 * i;
        int gb = ga + 1;
        float va[10], vb[10];
#pragma unroll
        for (int j = 0; j < 10; j++) {
            float2 v = unpack2(acc[j][i]);
            va[j] = v.x; vb[j] = v.y;
        }
        if (ga < N) {
            float* yl = Yl + (size_t)ga * 80;
            float* yr = Yr + (size_t)ga * 80;
#pragma unroll
            for (int j = 0; j < 5; j++) {
                yl[tx + 16 * j] = va[j];
                yr[tx + 16 * j] = va[5 + j];
            }
        }
        if (gb < N) {
            float* yl = Yl + (size_t)gb * 80;
            float* yr = Yr + (size_t)gb * 80;
#pragma unroll
            for (int j = 0; j < 5; j++) {
                yl[tx + 16 * j] = vb[j];
                yr[tx + 16 * j] = vb[5 + j];
            }
        }
    }
}

// ---------------- CSR build --------------------------------------------------
__global__ void hist_k(const int* __restrict__ ei) {
    int t = blockIdx.x * blockDim.x + threadIdx.x;
    if (t < EE) atomicAdd(&g_deg[ei[EE + t]], 1);
}

__global__ __launch_bounds__(1024) void scan_k() {
    __shared__ int warpsum[32];
    __shared__ int s_carry;
    const int tid = threadIdx.x;
    const int lane = tid & 31, wid = tid >> 5;
    if (tid == 0) s_carry = 0;
    __syncthreads();
    for (int base = 0; base < NN; base += 1024) {
        int i = base + tid;
        int v = (i < NN) ? g_deg[i] : 0;
        int incl = v;
#pragma unroll
        for (int o = 1; o < 32; o <<= 1) {
            int n = __shfl_up_sync(0xffffffffu, incl, o);
            if (lane >= o) incl += n;
        }
        if (lane == 31) warpsum[wid] = incl;
        __syncthreads();
        if (tid < 32) {
            int w = warpsum[tid];
            int wi = w;
#pragma unroll
            for (int o = 1; o < 32; o <<= 1) {
                int n = __shfl_up_sync(0xffffffffu, wi, o);
                if (tid >= o) wi += n;
            }
            warpsum[tid] = wi - w;
        }
        __syncthreads();
        int excl = s_carry + warpsum[wid] + incl - v;
        if (i < NN) { g_rowptr[i] = excl; g_cursor[i] = excl; }
        __syncthreads();
        if (tid == 1023) s_carry = excl + v;
        __syncthreads();
    }
    if (tid == 0) g_rowptr[NN] = s_carry;
}

__global__ void fill_k(const int* __restrict__ ei) {
    int t = blockIdx.x * blockDim.x + threadIdx.x;
    if (t >= EE) return;
    int s = ei[t], d = ei[EE + t];
    int p = atomicAdd(&g_cursor[d], 1);
    g_csr[p] = s;
}

// ---------------- degree-bucket sort (load balance for agg) ------------------
__global__ void bhist_k() {
    int t = blockIdx.x * blockDim.x + threadIdx.x;
    if (t < NN) atomicAdd(&g_bh[min(g_deg[t], 63)], 1);
}
__global__ void bscan_k() {     // one warp: exclusive scan of 64 bins
    int lane = threadIdx.x;
    int v0 = g_bh[lane], v1 = g_bh[32 + lane];
    int s0 = v0, s1 = v1;
#pragma unroll
    for (int o = 1; o < 32; o <<= 1) {
        int n0 = __shfl_up_sync(0xffffffffu, s0, o);
        int n1 = __shfl_up_sync(0xffffffffu, s1, o);
        if (lane >= o) { s0 += n0; s1 += n1; }
    }
    int tot0 = __shfl_sync(0xffffffffu, s0, 31);
    int e0 = s0 - v0;
    int e1 = tot0 + s1 - v1;
    g_bhoff[lane] = e0;      g_bcur[lane] = e0;
    g_bhoff[32 + lane] = e1; g_bcur[32 + lane] = e1;
}
__global__ void bfill_k() {
    int t = blockIdx.x * blockDim.x + threadIdx.x;
    if (t >= NN) return;
    int p = atomicAdd(&g_bcur[min(g_deg[t], 63)], 1);
    g_perm[p] = t;
}

// ---------------- fused attention aggregate (online softmax) -----------------
__global__ __launch_bounds__(256) void agg_k(const float* __restrict__ att,
                                             const float* __restrict__ bias,
                                             float* __restrict__ out) {
    int t = blockIdx.x * blockDim.x + threadIdx.x;
    if (t >= NN * H) return;
    int d = __ldg(&g_perm[t >> 3]);
    int h = t & 7;

    float xr_[10], at[10];
    {
        const float2* xrp = (const float2*)(g_xr + (size_t)d * HC + h * C);
        const float2* atp = (const float2*)(att + h * C);
#pragma unroll
        for (int i = 0; i < 5; i++) {
            float2 a = __ldg(xrp + i);
            xr_[2 * i] = a.x; xr_[2 * i + 1] = a.y;
            float2 w = __ldg(atp + i);
            at[2 * i] = w.x; at[2 * i + 1] = w.y;
        }
    }

    float acc[10];
    float m, ssum = 1.f;
    {
        const float2* xsp = (const float2*)(g_xl + (size_t)d * HC + h * C);
        float e = 0.f;
#pragma unroll
        for (int i = 0; i < 5; i++) {
            float2 a = __ldg(xsp + i);
            acc[2 * i] = a.x; acc[2 * i + 1] = a.y;
            float v0 = a.x + xr_[2 * i];     v0 = v0 > 0.f ? v0 : 0.2f * v0;
            float v1 = a.y + xr_[2 * i + 1]; v1 = v1 > 0.f ? v1 : 0.2f * v1;
            e += at[2 * i] * v0 + at[2 * i + 1] * v1;
        }
        m = e;
    }

    const int beg = __ldg(&g_rowptr[d]);
    const int end = __ldg(&g_rowptr[d + 1]);
    for (int j = beg; j < end; j++) {
        int s = __ldg(&g_csr[j]);
        const float2* xsp = (const float2*)(g_xl + (size_t)s * HC + h * C);
        float xs_[10];
        float e = 0.f;
#pragma unroll
        for (int i = 0; i < 5; i++) {
            float2 a = __ldg(xsp + i);
            xs_[2 * i] = a.x; xs_[2 * i + 1] = a.y;
            float v0 = a.x + xr_[2 * i];     v0 = v0 > 0.f ? v0 : 0.2f * v0;
            float v1 = a.y + xr_[2 * i + 1]; v1 = v1 > 0.f ? v1 : 0.2f * v1;
            e += at[2 * i] * v0 + at[2 * i + 1] * v1;
        }
        if (e <= m) {
            float p = __expf(e - m);
            ssum += p;
#pragma unroll
            for (int c = 0; c < 10; c++) acc[c] += p * xs_[c];
        } else {
            float r = __expf(m - e);
            ssum = ssum * r + 1.f;
#pragma unroll
            for (int c = 0; c < 10; c++) acc[c] = acc[c] * r + xs_[c];
            m = e;
        }
    }

    float inv = 1.f / ssum;
    float2* op = (float2*)(out + (size_t)d * HC + h * C);
#pragma unroll
    for (int i = 0; i < 5; i++) {
        float b0 = __ldg(bias + h * C + 2 * i);
        float b1 = __ldg(bias + h * C + 2 * i + 1);
        float v0 = acc[2 * i] * inv + b0;
        float v1 = acc[2 * i + 1] * inv + b1;
        v0 = v0 > 0.f ? v0 : expm1f(v0);
        v1 = v1 > 0.f ? v1 : expm1f(v1);
        op[i] = make_float2(v0, v1);
    }
}

// ---------------- launch -----------------------------------------------------
extern "C" void kernel_launch(void* const* d_in, const int* in_sizes, int n_in,
                              void* d_out, int out_size) {
    const float* x  = (const float*)d_in[0];
    const int*   ei = (const int*)d_in[1];
    const float* Wl[3]  = {(const float*)d_in[2], (const float*)d_in[6], (const float*)d_in[10]};
    const float* Wr[3]  = {(const float*)d_in[3], (const float*)d_in[7], (const float*)d_in[11]};
    const float* att[3] = {(const float*)d_in[4], (const float*)d_in[8], (const float*)d_in[12]};
    const float* bs[3]  = {(const float*)d_in[5], (const float*)d_in[9], (const float*)d_in[13]};

    const int N = NN;

    float *p_xl, *p_xr, *p_h;
    int *p_deg, *p_bh;
    cudaGetSymbolAddress((void**)&p_xl, g_xl);
    cudaGetSymbolAddress((void**)&p_xr, g_xr);
    cudaGetSymbolAddress((void**)&p_h, g_h);
    cudaGetSymbolAddress((void**)&p_deg, g_deg);
    cudaGetSymbolAddress((void**)&p_bh, g_bh);

    // ---- CSR + degree-sort build (once; reused by all 3 layers) ----
    cudaMemsetAsync(p_deg, 0, (size_t)NN * sizeof(int));
    cudaMemsetAsync(p_bh, 0, 64 * sizeof(int));
    hist_k<<<(EE + 255) / 256, 256>>>(ei);
    scan_k<<<1, 1024>>>();
    fill_k<<<(EE + 255) / 256, 256>>>(ei);
    bhist_k<<<(NN + 255) / 256, 256>>>();
    bscan_k<<<1, 32>>>();
    bfill_k<<<(NN + 255) / 256, 256>>>();

    const int smem128 = (32 * 132) * 4 + (32 * 160) * 8;   // 57856
    const int smem80  = (40 * 132) * 4 + (40 * 160) * 8;   // 72320
    cudaFuncSetAttribute(gemm2<128, 32>, cudaFuncAttributeMaxDynamicSharedMemorySize, smem128);
    cudaFuncSetAttribute(gemm2<80, 40>,  cudaFuncAttributeMaxDynamicSharedMemorySize, smem80);

    const int gemmGrid = (N + 127) / 128;
    const int aggBlocks = (NN * H + 255) / 256;

    const float* xin = x;
    for (int l = 0; l < 3; l++) {
        if (l == 0)
            gemm2<128, 32><<<gemmGrid, 256, smem128>>>(xin, Wl[l], Wr[l], p_xl, p_xr, N);
        else
            gemm2<80, 40><<<gemmGrid, 256, smem80>>>(xin, Wl[l], Wr[l], p_xl, p_xr, N);
        float* xout = (l == 2) ? (float*)d_out : p_h;
        agg_k<<<aggBlocks, 256>>>(att[l], bs[l], xout);
        xin = p_h;
    }
}